// round 12
// baseline (speedup 1.0000x reference)
#include <cuda_runtime.h>
#include <cstdint>

#define BB    2048
#define TSEQ  512
#define HH    51
#define TTOT  544      // TSEQ + 32 future
#define NCTA  152      // one CTA per SM on GB300
#define NBIG  72       // first 72 CTAs take 14 elements, remaining 80 take 13
#define EPCMX 14
#define NTHR  256      // 2 groups x 64 j x 2 gate-split
#define MPT   7        // elements per thread
#define WROW  232      // floats per j-row (conflict-free LDS.128: 232 % 32 == 8)
#define NROW  52       // 51 real j rows + row 51 = wlin output row (in W2h)
#define HROW  56       // floats per element row in h arrays

#define W_SZ   (NROW * WROW)    // 12064 floats per weight matrix
#define XS_SZ  (EPCMX * TSEQ)   // 7168
#define HD_SZ  (EPCMX * HROW)   // 784
#define SM_FLOATS (3*W_SZ + XS_SZ + 2*HD_SZ + 256 + 256 + 256 + 16)
#define SM_BYTES  (SM_FLOATS * 4)

// ---------------- packed f32x2 helpers ----------------
__device__ __forceinline__ unsigned long long ffma2(unsigned long long a,
                                                    unsigned long long b,
                                                    unsigned long long c) {
    unsigned long long d;
    asm("fma.rn.f32x2 %0, %1, %2, %3;" : "=l"(d) : "l"(a), "l"(b), "l"(c));
    return d;
}
__device__ __forceinline__ float2 unpack2(unsigned long long v) {
    float2 r;
    asm("mov.b64 {%0, %1}, %2;" : "=f"(r.x), "=f"(r.y) : "l"(v));
    return r;
}
__device__ __forceinline__ float sigf(float x) {
    return __fdividef(1.0f, 1.0f + __expf(-x));
}
__device__ __forceinline__ float tanhf_fast(float x) {
    return __fdividef(2.0f, 1.0f + __expf(-2.0f * x)) - 1.0f;
}

// single matvec: acc{A,B}[m] += W[j, gate-slots(gs, gs+2), :] . h[e0+m, :]
__device__ __forceinline__ void matvec_acc(const float* __restrict__ Wrow,
                                           const float* __restrict__ hbase,
                                           unsigned long long aA[MPT],
                                           unsigned long long aB[MPT]) {
#pragma unroll
    for (int q = 0; q < 13; q++) {
        ulonglong2 wa = *(const ulonglong2*)(Wrow + q * 16);
        ulonglong2 wb = *(const ulonglong2*)(Wrow + q * 16 + 8);
#pragma unroll
        for (int m = 0; m < MPT; m++) {
            ulonglong2 hp = *(const ulonglong2*)(hbase + m * HROW + q * 4);
            aA[m] = ffma2(wa.x, hp.x, aA[m]);
            aB[m] = ffma2(wa.y, hp.x, aB[m]);
            aA[m] = ffma2(wb.x, hp.y, aA[m]);
            aB[m] = ffma2(wb.y, hp.y, aB[m]);
        }
    }
}

// shared-operand dual matvec: TWO weight matrices against the SAME h vector.
__device__ __forceinline__ void matvec_dual_sh(const float* __restrict__ Wr1,
                                               const float* __restrict__ Wr2,
                                               const float* __restrict__ h,
                                               unsigned long long aA[MPT],
                                               unsigned long long aB[MPT],
                                               unsigned long long aC[MPT],
                                               unsigned long long aD[MPT]) {
#pragma unroll
    for (int q = 0; q < 13; q++) {
        ulonglong2 wa1 = *(const ulonglong2*)(Wr1 + q * 16);
        ulonglong2 wb1 = *(const ulonglong2*)(Wr1 + q * 16 + 8);
        ulonglong2 wa2 = *(const ulonglong2*)(Wr2 + q * 16);
        ulonglong2 wb2 = *(const ulonglong2*)(Wr2 + q * 16 + 8);
#pragma unroll
        for (int m = 0; m < MPT; m++) {
            ulonglong2 hp = *(const ulonglong2*)(h + m * HROW + q * 4);
            aA[m] = ffma2(wa1.x, hp.x, aA[m]);
            aB[m] = ffma2(wa1.y, hp.x, aB[m]);
            aC[m] = ffma2(wa2.x, hp.x, aC[m]);
            aD[m] = ffma2(wa2.y, hp.x, aD[m]);
            aA[m] = ffma2(wb1.x, hp.y, aA[m]);
            aB[m] = ffma2(wb1.y, hp.y, aB[m]);
            aC[m] = ffma2(wb2.x, hp.y, aC[m]);
            aD[m] = ffma2(wb2.y, hp.y, aD[m]);
        }
    }
}

__global__ void __launch_bounds__(NTHR, 1)
lstm_seq_kernel(const float* __restrict__ input,
                const float* __restrict__ Wih1, const float* __restrict__ Whh1,
                const float* __restrict__ bih1, const float* __restrict__ bhh1,
                const float* __restrict__ Wih2, const float* __restrict__ Whh2,
                const float* __restrict__ bih2, const float* __restrict__ bhh2,
                const float* __restrict__ Wlin, const float* __restrict__ blin,
                float* __restrict__ out) {
    extern __shared__ float sm[];
    float* W1    = sm;                 // gate slots per (kb): [gs0 pair][gs1 pair]
    float* W2i   = W1  + W_SZ;
    float* W2h   = W2i + W_SZ;         // row 51 gate-slot0 = wlin (output row)
    float* xs    = W2h + W_SZ;         // [14][512]
    float* hd1   = xs  + XS_SZ;        // [14][56]
    float* hd2   = hd1 + HD_SZ;        // [14][56]
    float* wih1q = hd2 + HD_SZ;        // [64][4] gate order i,f,g,o
    float* b1q   = wih1q + 256;
    float* b2q   = b1q   + 256;
    float* ovF   = b2q   + 256;        // [16] feedback distribution buffer

    const int tid = threadIdx.x;
    const int g   = tid >> 7;
    const int r   = tid & 127;
    const int j   = r >> 1;
    const int gs  = r & 1;              // gs0 -> gates (i,g); gs1 -> gates (f,o)
    const int jj  = (j < NROW) ? j : (NROW - 1);
    const int cta = blockIdx.x;
    const int big = (cta < NBIG);
    const int epc = big ? 14 : 13;
    const int b0  = big ? cta * 14 : NBIG * 14 + (cta - NBIG) * 13;
    const int e0  = g * MPT;

    // a2 activation: gs0 -> tanh (gate g), gs1 -> sigmoid (gate o). a1 always sigmoid.
    const float kmul = gs ? -1.0f : -2.0f;
    const float kA   = gs ?  1.0f :  2.0f;
    const float kB   = gs ?  0.0f : -1.0f;

    // ---------- one-time init ----------
    // gate gg -> slot offset (gg&1)*4 + (gg>>1)*2 : pairs (i,g) at gs0, (f,o) at gs1
    for (int idx = tid; idx < NROW * 26; idx += NTHR) {
        int jr = idx / 26;
        int kb = idx - jr * 26;
#pragma unroll
        for (int gg = 0; gg < 4; gg++) {
#pragma unroll
            for (int s = 0; s < 2; s++) {
                int k = 2 * kb + s;
                bool ok = (k < HH);
                int o = jr * WROW + kb * 8 + (gg & 1) * 4 + (gg >> 1) * 2 + s;
                float v1 = 0.f, v2 = 0.f, v3 = 0.f;
                if (jr < HH && ok) {
                    int rr = gg * HH + jr;
                    v1 = Whh1[rr * HH + k];
                    v2 = Wih2[rr * HH + k];
                    v3 = Whh2[rr * HH + k];
                } else if (jr == HH && gg == 0 && ok) {
                    v3 = Wlin[k];                       // output row in W2h
                }
                W1 [o] = v1;
                W2i[o] = v2;
                W2h[o] = v3;
            }
        }
    }
    if (tid < 64) {
#pragma unroll
        for (int gg = 0; gg < 4; gg++) {
            bool ok = tid < HH;
            wih1q[tid * 4 + gg] = ok ? Wih1[gg * HH + tid] : 0.f;
            b1q  [tid * 4 + gg] = ok ? (bih1[gg * HH + tid] + bhh1[gg * HH + tid]) : 0.f;
            b2q  [tid * 4 + gg] = ok ? (bih2[gg * HH + tid] + bhh2[gg * HH + tid]) : 0.f;
        }
    }
    for (int idx = tid; idx < XS_SZ; idx += NTHR) {
        int e = idx >> 9, tc = idx & 511;
        xs[idx] = (e < epc) ? input[(size_t)(b0 + e) * TSEQ + tc] : 0.f;
    }
    for (int idx = tid; idx < 2 * HD_SZ; idx += NTHR) hd1[idx] = 0.f;
    if (tid < 16) ovF[tid] = 0.f;
    const float blin_r = blin[0];
    __syncthreads();

    float c1[MPT], c2[MPT], z2A[MPT], z2B[MPT];
#pragma unroll
    for (int m = 0; m < MPT; m++) { c1[m] = 0.f; c2[m] = 0.f; z2A[m] = 0.f; z2B[m] = 0.f; }

    const float*  W1r  = W1  + jj * WROW + gs * 4;
    const float*  W2ir = W2i + jj * WROW + gs * 4;
    const float*  W2hr = W2h + jj * WROW + gs * 4;
    // my 2 gates: (gs, gs+2) in i,f,g,o order
    const float2  wxp  = make_float2(wih1q[jj * 4 + gs], wih1q[jj * 4 + 2 + gs]);
    const float2  bp1  = make_float2(b1q  [jj * 4 + gs], b1q  [jj * 4 + 2 + gs]);
    const float2  bp2  = make_float2(b2q  [jj * 4 + gs], b2q  [jj * 4 + 2 + gs]);
    const bool    outown = (r == 2 * HH);   // j==51, gs==0: output-row owner
    const float*  hd1g = hd1 + e0 * HROW;
    const float*  hd2g = hd2 + e0 * HROW;

    // ---------- prologue: h1(0) (h1(-1) = c1(-1) = 0) ----------
#pragma unroll
    for (int m = 0; m < MPT; m++) {
        float x0 = xs[(e0 + m) * TSEQ];
        float zA = fmaf(wxp.x, x0, bp1.x);
        float zB = fmaf(wxp.y, x0, bp1.y);
        float a1 = sigf(zA);                                             // i | f
        float a2 = kA * __fdividef(1.0f, 1.0f + __expf(kmul * zB)) + kB; // g | o
        float ig  = a1 * a2;                        // valid gs0: i*g
        float igr = __shfl_xor_sync(0xffffffffu, ig, 1);
        c1[m] = igr;                                // valid gs1: f*0 + i*g
        float h1n = a2 * tanhf_fast(c1[m]);         // valid gs1: o*tanh(c)
        if (gs == 1 && j < HH)
            hd1[(e0 + m) * HROW + j] = h1n;
    }
    __syncthreads();                                // h1(0) visible

    // ---------- pipelined scan: iteration t emits h2(t), out(t), h1(t+1) ----------
    for (int t = 0; t < TTOT; t++) {
        // ---- phase A: dual over h1(t): mv2i(t) -> aA/aB, mv1(t+1) -> aC/aD ----
        unsigned long long aA[MPT], aB[MPT], aC[MPT], aD[MPT];
#pragma unroll
        for (int m = 0; m < MPT; m++) { aA[m] = 0; aB[m] = 0; aC[m] = 0; aD[m] = 0; }
        matvec_dual_sh(W2ir, W1r, hd1g, aA, aB, aC, aD);

        float z1A[MPT], z1B[MPT];                   // compress mv1(t+1) partials
#pragma unroll
        for (int m = 0; m < MPT; m++) {
            float2 vc = unpack2(aC[m]); z1A[m] = vc.x + vc.y;
            float2 vd = unpack2(aD[m]); z1B[m] = vd.x + vd.y;
        }

        // ---- combine2: h2(t) (uses z2 = mv2h(t) partials from phase B(t-1)) ----
#pragma unroll
        for (int m = 0; m < MPT; m++) {
            float2 va = unpack2(aA[m]);
            float2 vb = unpack2(aB[m]);
            float zA = va.x + va.y + z2A[m] + bp2.x;
            float zB = vb.x + vb.y + z2B[m] + bp2.y;
            float a1 = sigf(zA);                                             // i | f
            float a2 = kA * __fdividef(1.0f, 1.0f + __expf(kmul * zB)) + kB; // g | o
            float ig  = a1 * a2;
            float igr = __shfl_xor_sync(0xffffffffu, ig, 1);
            c2[m] = fmaf(a1, c2[m], igr);           // valid gs1
            float h2n = a2 * tanhf_fast(c2[m]);     // valid gs1
            if (gs == 1 && j < HH)
                hd2[(e0 + m) * HROW + j] = h2n;
        }
        __syncthreads();                            // BAR-A: h2(t) visible

        // teacher-forced x(t+1)
        float xm[MPT];
        if (t + 1 < TSEQ) {
#pragma unroll
            for (int m = 0; m < MPT; m++) xm[m] = xs[(e0 + m) * TSEQ + (t + 1)];
        }

        // ---- phase B: mv2h(t+1) over h2(t); row 51 slot0 = wlin -> out(t) ----
#pragma unroll
        for (int m = 0; m < MPT; m++) { aA[m] = 0; aB[m] = 0; }
        matvec_acc(W2hr, hd2g, aA, aB);
#pragma unroll
        for (int m = 0; m < MPT; m++) {
            float2 va = unpack2(aA[m]); z2A[m] = va.x + va.y;
            float2 vb = unpack2(aB[m]); z2B[m] = vb.x + vb.y;
        }

        // output-row owner emits out(t) directly from its accumulator
        if (outown) {
#pragma unroll
            for (int m = 0; m < MPT; m++) {
                float o_t = z2A[m] + blin_r;
                if (e0 + m < epc)
                    out[(size_t)(b0 + e0 + m) * TTOT + t] = o_t;
                ovF[e0 + m] = o_t;                  // for feedback distribution
            }
        }
        if (t + 1 >= TSEQ) {                        // feedback steps: x(t+1) = out(t)
            __syncthreads();
#pragma unroll
            for (int m = 0; m < MPT; m++) xm[m] = ovF[e0 + m];
        }

        // ---- combine1: h1(t+1) from mv1 partials + x(t+1) ----
#pragma unroll
        for (int m = 0; m < MPT; m++) {
            float zA = z1A[m] + fmaf(wxp.x, xm[m], bp1.x);
            float zB = z1B[m] + fmaf(wxp.y, xm[m], bp1.y);
            float a1 = sigf(zA);
            float a2 = kA * __fdividef(1.0f, 1.0f + __expf(kmul * zB)) + kB;
            float ig  = a1 * a2;
            float igr = __shfl_xor_sync(0xffffffffu, ig, 1);
            c1[m] = fmaf(a1, c1[m], igr);
            float h1n = a2 * tanhf_fast(c1[m]);
            if (gs == 1 && j < HH)
                hd1[(e0 + m) * HROW + j] = h1n;
        }
        __syncthreads();                            // BAR-B: h1(t+1) visible
    }
}

extern "C" void kernel_launch(void* const* d_in, const int* in_sizes, int n_in,
                              void* d_out, int out_size) {
    const float* input = (const float*)d_in[0];
    const float* Wih1  = (const float*)d_in[1];
    const float* Whh1  = (const float*)d_in[2];
    const float* bih1  = (const float*)d_in[3];
    const float* bhh1  = (const float*)d_in[4];
    const float* Wih2  = (const float*)d_in[5];
    const float* Whh2  = (const float*)d_in[6];
    const float* bih2  = (const float*)d_in[7];
    const float* bhh2  = (const float*)d_in[8];
    const float* Wlin  = (const float*)d_in[9];
    const float* blin  = (const float*)d_in[10];
    // d_in[11] = "future" (=32), baked in as a constant.

    cudaFuncSetAttribute(lstm_seq_kernel,
                         cudaFuncAttributeMaxDynamicSharedMemorySize, SM_BYTES);
    lstm_seq_kernel<<<NCTA, NTHR, SM_BYTES>>>(input, Wih1, Whh1, bih1, bhh1,
                                              Wih2, Whh2, bih2, bhh2,
                                              Wlin, blin, (float*)d_out);
}

// round 13
// speedup vs baseline: 1.3194x; 1.3194x over previous
#include <cuda_runtime.h>
#include <cstdint>

#define BB    2048
#define TSEQ  512
#define HH    51
#define TTOT  544      // TSEQ + 32 future
#define NCTA  152      // one CTA per SM on GB300
#define NBIG  72       // first 72 CTAs take 14 elements, remaining 80 take 13
#define EPCMX 14
#define NTHR  256      // 2 groups x 64 j x 2 gate-split
#define MPT   7        // elements per thread
#define WROW  232      // floats per j-row (conflict-free LDS.128: 232 % 32 == 8)
#define NROW  52       // 51 real j rows + row 51 = wlin output row (in W2h)
#define HROW  56       // floats per element row in h arrays

#define W_SZ   (NROW * WROW)    // 12064 floats per weight matrix
#define XS_SZ  (EPCMX * TSEQ)   // 7168
#define HD_SZ  (EPCMX * HROW)   // 784
#define SM_FLOATS (3*W_SZ + XS_SZ + 2*HD_SZ + 256 + 256 + 256 + 16)
#define SM_BYTES  (SM_FLOATS * 4)

// ---------------- packed f32x2 helpers ----------------
__device__ __forceinline__ unsigned long long ffma2(unsigned long long a,
                                                    unsigned long long b,
                                                    unsigned long long c) {
    unsigned long long d;
    asm("fma.rn.f32x2 %0, %1, %2, %3;" : "=l"(d) : "l"(a), "l"(b), "l"(c));
    return d;
}
__device__ __forceinline__ float2 unpack2(unsigned long long v) {
    float2 r;
    asm("mov.b64 {%0, %1}, %2;" : "=f"(r.x), "=f"(r.y) : "l"(v));
    return r;
}
// ---------------- HW tanh activations (MUFU.TANH) ----------------
__device__ __forceinline__ float tanh_ap(float x) {
    float y;
    asm("tanh.approx.f32 %0, %1;" : "=f"(y) : "f"(x));
    return y;
}
__device__ __forceinline__ float sig_ap(float x) {
    return fmaf(0.5f, tanh_ap(0.5f * x), 0.5f);
}

// single matvec: acc{A,B}[m] += W[j, gate-slots(gs, gs+2), :] . h[e0+m, :]
__device__ __forceinline__ void matvec_acc(const float* __restrict__ Wrow,
                                           const float* __restrict__ hbase,
                                           unsigned long long aA[MPT],
                                           unsigned long long aB[MPT]) {
#pragma unroll
    for (int q = 0; q < 13; q++) {
        ulonglong2 wa = *(const ulonglong2*)(Wrow + q * 16);
        ulonglong2 wb = *(const ulonglong2*)(Wrow + q * 16 + 8);
#pragma unroll
        for (int m = 0; m < MPT; m++) {
            ulonglong2 hp = *(const ulonglong2*)(hbase + m * HROW + q * 4);
            aA[m] = ffma2(wa.x, hp.x, aA[m]);
            aB[m] = ffma2(wa.y, hp.x, aB[m]);
            aA[m] = ffma2(wb.x, hp.y, aA[m]);
            aB[m] = ffma2(wb.y, hp.y, aB[m]);
        }
    }
}

// shared-operand dual matvec: TWO weight matrices against the SAME h vector.
__device__ __forceinline__ void matvec_dual_sh(const float* __restrict__ Wr1,
                                               const float* __restrict__ Wr2,
                                               const float* __restrict__ h,
                                               unsigned long long aA[MPT],
                                               unsigned long long aB[MPT],
                                               unsigned long long aC[MPT],
                                               unsigned long long aD[MPT]) {
#pragma unroll
    for (int q = 0; q < 13; q++) {
        ulonglong2 wa1 = *(const ulonglong2*)(Wr1 + q * 16);
        ulonglong2 wb1 = *(const ulonglong2*)(Wr1 + q * 16 + 8);
        ulonglong2 wa2 = *(const ulonglong2*)(Wr2 + q * 16);
        ulonglong2 wb2 = *(const ulonglong2*)(Wr2 + q * 16 + 8);
#pragma unroll
        for (int m = 0; m < MPT; m++) {
            ulonglong2 hp = *(const ulonglong2*)(h + m * HROW + q * 4);
            aA[m] = ffma2(wa1.x, hp.x, aA[m]);
            aB[m] = ffma2(wa1.y, hp.x, aB[m]);
            aC[m] = ffma2(wa2.x, hp.x, aC[m]);
            aD[m] = ffma2(wa2.y, hp.x, aD[m]);
            aA[m] = ffma2(wb1.x, hp.y, aA[m]);
            aB[m] = ffma2(wb1.y, hp.y, aB[m]);
            aC[m] = ffma2(wb2.x, hp.y, aC[m]);
            aD[m] = ffma2(wb2.y, hp.y, aD[m]);
        }
    }
}

__global__ void __launch_bounds__(NTHR, 1)
lstm_seq_kernel(const float* __restrict__ input,
                const float* __restrict__ Wih1, const float* __restrict__ Whh1,
                const float* __restrict__ bih1, const float* __restrict__ bhh1,
                const float* __restrict__ Wih2, const float* __restrict__ Whh2,
                const float* __restrict__ bih2, const float* __restrict__ bhh2,
                const float* __restrict__ Wlin, const float* __restrict__ blin,
                float* __restrict__ out) {
    extern __shared__ float sm[];
    float* W1    = sm;                 // gate slots per (kb): [gs0 pair][gs1 pair]
    float* W2i   = W1  + W_SZ;
    float* W2h   = W2i + W_SZ;         // row 51 gate-slot0 = wlin (output row)
    float* xs    = W2h + W_SZ;         // [14][512]
    float* hd1   = xs  + XS_SZ;        // [14][56]
    float* hd2   = hd1 + HD_SZ;        // [14][56]
    float* wih1q = hd2 + HD_SZ;        // [64][4] gate order i,f,g,o
    float* b1q   = wih1q + 256;
    float* b2q   = b1q   + 256;
    float* ovF   = b2q   + 256;        // [16] feedback distribution buffer

    const int tid = threadIdx.x;
    const int g   = tid >> 7;
    const int r   = tid & 127;
    const int j   = r >> 1;
    const int gs  = r & 1;              // gs0 -> gates (i,g); gs1 -> gates (f,o)
    const int jj  = (j < NROW) ? j : (NROW - 1);
    const int cta = blockIdx.x;
    const int big = (cta < NBIG);
    const int epc = big ? 14 : 13;
    const int b0  = big ? cta * 14 : NBIG * 14 + (cta - NBIG) * 13;
    const int e0  = g * MPT;

    // a2 = cA * tanh(cM * z) + cB : gs0 -> tanh (gate g), gs1 -> sigmoid (gate o)
    const float cM = gs ? 0.5f : 1.0f;
    const float cA = gs ? 0.5f : 1.0f;
    const float cB = gs ? 0.5f : 0.0f;

    // ---------- one-time init ----------
    // gate gg -> slot offset (gg&1)*4 + (gg>>1)*2 : pairs (i,g) at gs0, (f,o) at gs1
    for (int idx = tid; idx < NROW * 26; idx += NTHR) {
        int jr = idx / 26;
        int kb = idx - jr * 26;
#pragma unroll
        for (int gg = 0; gg < 4; gg++) {
#pragma unroll
            for (int s = 0; s < 2; s++) {
                int k = 2 * kb + s;
                bool ok = (k < HH);
                int o = jr * WROW + kb * 8 + (gg & 1) * 4 + (gg >> 1) * 2 + s;
                float v1 = 0.f, v2 = 0.f, v3 = 0.f;
                if (jr < HH && ok) {
                    int rr = gg * HH + jr;
                    v1 = Whh1[rr * HH + k];
                    v2 = Wih2[rr * HH + k];
                    v3 = Whh2[rr * HH + k];
                } else if (jr == HH && gg == 0 && ok) {
                    v3 = Wlin[k];                       // output row in W2h
                }
                W1 [o] = v1;
                W2i[o] = v2;
                W2h[o] = v3;
            }
        }
    }
    if (tid < 64) {
#pragma unroll
        for (int gg = 0; gg < 4; gg++) {
            bool ok = tid < HH;
            wih1q[tid * 4 + gg] = ok ? Wih1[gg * HH + tid] : 0.f;
            b1q  [tid * 4 + gg] = ok ? (bih1[gg * HH + tid] + bhh1[gg * HH + tid]) : 0.f;
            b2q  [tid * 4 + gg] = ok ? (bih2[gg * HH + tid] + bhh2[gg * HH + tid]) : 0.f;
        }
    }
    for (int idx = tid; idx < XS_SZ; idx += NTHR) {
        int e = idx >> 9, tc = idx & 511;
        xs[idx] = (e < epc) ? input[(size_t)(b0 + e) * TSEQ + tc] : 0.f;
    }
    for (int idx = tid; idx < 2 * HD_SZ; idx += NTHR) hd1[idx] = 0.f;
    if (tid < 16) ovF[tid] = 0.f;
    const float blin_r = blin[0];
    __syncthreads();

    float c1[MPT], c2[MPT], z2A[MPT], z2B[MPT];
#pragma unroll
    for (int m = 0; m < MPT; m++) { c1[m] = 0.f; c2[m] = 0.f; z2A[m] = 0.f; z2B[m] = 0.f; }

    const float*  W1r  = W1  + jj * WROW + gs * 4;
    const float*  W2ir = W2i + jj * WROW + gs * 4;
    const float*  W2hr = W2h + jj * WROW + gs * 4;
    // my 2 gates: (gs, gs+2) in i,f,g,o order
    const float2  wxp  = make_float2(wih1q[jj * 4 + gs], wih1q[jj * 4 + 2 + gs]);
    const float2  bp1  = make_float2(b1q  [jj * 4 + gs], b1q  [jj * 4 + 2 + gs]);
    const float2  bp2  = make_float2(b2q  [jj * 4 + gs], b2q  [jj * 4 + 2 + gs]);
    const bool    outown = (r == 2 * HH);   // j==51, gs==0: output-row owner
    const float*  hd1g = hd1 + e0 * HROW;
    const float*  hd2g = hd2 + e0 * HROW;

    // ---------- prologue: h1(0) (h1(-1) = c1(-1) = 0) ----------
#pragma unroll
    for (int m = 0; m < MPT; m++) {
        float x0 = xs[(e0 + m) * TSEQ];
        float zA = fmaf(wxp.x, x0, bp1.x);
        float zB = fmaf(wxp.y, x0, bp1.y);
        float a1 = sig_ap(zA);                          // i | f
        float a2 = fmaf(cA, tanh_ap(cM * zB), cB);      // g | o
        float ig  = a1 * a2;                            // valid gs0: i*g
        float igr = __shfl_xor_sync(0xffffffffu, ig, 1);
        c1[m] = igr;                                    // valid gs1: f*0 + i*g
        float h1n = a2 * tanh_ap(c1[m]);                // valid gs1: o*tanh(c)
        if (gs == 1 && j < HH)
            hd1[(e0 + m) * HROW + j] = h1n;
    }
    __syncthreads();                                    // h1(0) visible

    // ---------- pipelined scan: iteration t emits h2(t), out(t), h1(t+1) ----------
    for (int t = 0; t < TTOT; t++) {
        // ---- phase A: dual over h1(t): mv2i(t) -> aA/aB, mv1(t+1) -> aC/aD ----
        unsigned long long aA[MPT], aB[MPT], aC[MPT], aD[MPT];
#pragma unroll
        for (int m = 0; m < MPT; m++) { aA[m] = 0; aB[m] = 0; aC[m] = 0; aD[m] = 0; }
        matvec_dual_sh(W2ir, W1r, hd1g, aA, aB, aC, aD);

        float z1A[MPT], z1B[MPT];                       // compress mv1(t+1) partials
#pragma unroll
        for (int m = 0; m < MPT; m++) {
            float2 vc = unpack2(aC[m]); z1A[m] = vc.x + vc.y;
            float2 vd = unpack2(aD[m]); z1B[m] = vd.x + vd.y;
        }

        // ---- combine2: h2(t) (uses z2 = mv2h(t) partials from phase B(t-1)) ----
#pragma unroll
        for (int m = 0; m < MPT; m++) {
            float2 va = unpack2(aA[m]);
            float2 vb = unpack2(aB[m]);
            float zA = va.x + va.y + z2A[m] + bp2.x;
            float zB = vb.x + vb.y + z2B[m] + bp2.y;
            float a1 = sig_ap(zA);                      // i | f
            float a2 = fmaf(cA, tanh_ap(cM * zB), cB);  // g | o
            float ig  = a1 * a2;
            float igr = __shfl_xor_sync(0xffffffffu, ig, 1);
            c2[m] = fmaf(a1, c2[m], igr);               // valid gs1
            float h2n = a2 * tanh_ap(c2[m]);            // valid gs1
            if (gs == 1 && j < HH)
                hd2[(e0 + m) * HROW + j] = h2n;
        }
        __syncthreads();                                // BAR-A: h2(t) visible

        // teacher-forced x(t+1)
        float xm[MPT];
        if (t + 1 < TSEQ) {
#pragma unroll
            for (int m = 0; m < MPT; m++) xm[m] = xs[(e0 + m) * TSEQ + (t + 1)];
        }

        // ---- phase B: mv2h(t+1) over h2(t); row 51 slot0 = wlin -> out(t) ----
#pragma unroll
        for (int m = 0; m < MPT; m++) { aA[m] = 0; aB[m] = 0; }
        matvec_acc(W2hr, hd2g, aA, aB);
#pragma unroll
        for (int m = 0; m < MPT; m++) {
            float2 va = unpack2(aA[m]); z2A[m] = va.x + va.y;
            float2 vb = unpack2(aB[m]); z2B[m] = vb.x + vb.y;
        }

        // output-row owner emits out(t) directly from its accumulator
        if (outown) {
#pragma unroll
            for (int m = 0; m < MPT; m++) {
                float o_t = z2A[m] + blin_r;
                if (e0 + m < epc)
                    out[(size_t)(b0 + e0 + m) * TTOT + t] = o_t;
                ovF[e0 + m] = o_t;                      // for feedback distribution
            }
        }
        if (t + 1 >= TSEQ) {                            // feedback steps: x(t+1) = out(t)
            __syncthreads();
#pragma unroll
            for (int m = 0; m < MPT; m++) xm[m] = ovF[e0 + m];
        }

        // ---- combine1: h1(t+1) from mv1 partials + x(t+1) ----
#pragma unroll
        for (int m = 0; m < MPT; m++) {
            float zA = z1A[m] + fmaf(wxp.x, xm[m], bp1.x);
            float zB = z1B[m] + fmaf(wxp.y, xm[m], bp1.y);
            float a1 = sig_ap(zA);
            float a2 = fmaf(cA, tanh_ap(cM * zB), cB);
            float ig  = a1 * a2;
            float igr = __shfl_xor_sync(0xffffffffu, ig, 1);
            c1[m] = fmaf(a1, c1[m], igr);
            float h1n = a2 * tanh_ap(c1[m]);
            if (gs == 1 && j < HH)
                hd1[(e0 + m) * HROW + j] = h1n;
        }
        __syncthreads();                                // BAR-B: h1(t+1) visible
    }
}

extern "C" void kernel_launch(void* const* d_in, const int* in_sizes, int n_in,
                              void* d_out, int out_size) {
    const float* input = (const float*)d_in[0];
    const float* Wih1  = (const float*)d_in[1];
    const float* Whh1  = (const float*)d_in[2];
    const float* bih1  = (const float*)d_in[3];
    const float* bhh1  = (const float*)d_in[4];
    const float* Wih2  = (const float*)d_in[5];
    const float* Whh2  = (const float*)d_in[6];
    const float* bih2  = (const float*)d_in[7];
    const float* bhh2  = (const float*)d_in[8];
    const float* Wlin  = (const float*)d_in[9];
    const float* blin  = (const float*)d_in[10];
    // d_in[11] = "future" (=32), baked in as a constant.

    cudaFuncSetAttribute(lstm_seq_kernel,
                         cudaFuncAttributeMaxDynamicSharedMemorySize, SM_BYTES);
    lstm_seq_kernel<<<NCTA, NTHR, SM_BYTES>>>(input, Wih1, Whh1, bih1, bhh1,
                                              Wih2, Whh2, bih2, bhh2,
                                              Wlin, blin, (float*)d_out);
}